// round 17
// baseline (speedup 1.0000x reference)
#include <cuda_runtime.h>
#include <cuda_bf16.h>

// ---- static problem config ----
#define NIMG 32
#define HH   1024
#define WW   1024
#define BHW  16                 // pool window
#define BSTR 14                 // block stride
#define BC   73                 // blocks per spatial dim
#define BC2  (BC*BC)            // 5329
#define NROW (NIMG*BC)          // 2336  (n, bh) row-blocks
#define NBLK (NROW*BC)          // 170528 total blocks
#define OUT_ELEMS (NBLK*3)      // 511584 floats = 127896 float4 (exact)
#define OUT_VEC4  (OUT_ELEMS/4)
#define THRESH 0.9f
#define W4     (WW/4)

// scratch (device globals — no allocation allowed; zero-initialized)
__device__ unsigned g_bitmap[NROW * 3];     // 96-bit active mask per (n,bh) row
__device__ unsigned g_count[NROW];          // popcount per row
__device__ unsigned g_offset[NROW];         // sparse fallback scan (cold)
__device__ unsigned long long g_state;      // (done_ctas << 32) | acc_count

__device__ __forceinline__ float4 fmax4(float4 a, float4 b)
{
    return make_float4(fmaxf(a.x, b.x), fmaxf(a.y, b.y),
                       fmaxf(a.z, b.z), fmaxf(a.w, b.w));
}

__device__ __forceinline__ int nth_set_bit(unsigned w, int n)  // n-th (0-based)
{
    return (int)__fns(w, 0, n + 1);
}

__device__ __forceinline__ float4 phase_pack(int phase,
                                             float a0, float a1, float a2,
                                             float b0, float b1, float b2)
{
    if (phase == 0) return make_float4(a0, a1, a2, b0);
    if (phase == 1) return make_float4(a1, a2, b0, b1);
    return make_float4(a2, b0, b1, b2);
}

// Horizontal checkpoint: publish column maxima, compute 73 window maxima,
// ballot into sbm, return whether ALL windows are active. All 128 threads.
__device__ __forceinline__ bool checkpoint(float4 a0, float4 a1,
                                           float4* __restrict__ sv4,
                                           unsigned* __restrict__ sbm, int tid)
{
    sv4[tid]       = a0;
    sv4[tid + 128] = a1;
    __syncthreads();
    const float* sv = (const float*)sv4;
    if (tid < 96) {                       // warps 0,1,2
        float m = 0.f;
        if (tid < BC) {
            const int w0 = tid * BSTR - 1;
            const int ws = (w0 < 0) ? 0 : w0;
            const int we = (w0 + BHW < WW) ? (w0 + BHW) : WW;
            for (int w = ws; w < we; ++w) m = fmaxf(m, sv[w]);
        }
        unsigned b = __ballot_sync(0xFFFFFFFFu, m > THRESH);
        if ((tid & 31) == 0) sbm[tid >> 5] = b;
    }
    __syncthreads();
    return (sbm[0] == 0xFFFFFFFFu) &
           (sbm[1] == 0xFFFFFFFFu) &
           (sbm[2] == 0x1FFu);
}

// COLD sparse fallback: the last CTA rewrites the entire output. Scans the
// 2336 counts (partials in smem, offsets in g_offset), then grid-strides all
// output slots with binary search + bitmap bit-ranking. Never taken on the
// bench input; kept for correctness on arbitrary inputs.
__device__ __noinline__ void sparse_rewrite(float4* __restrict__ out,
                                            unsigned total, int tid)
{
    __shared__ unsigned s_part[128];
    const int CH = (NROW + 127) / 128;   // 19

    const int start = tid * CH;
    const int end   = (start + CH < NROW) ? (start + CH) : NROW;
    unsigned sum = 0;
    for (int i = start; i < end; ++i) sum += g_count[i];
    s_part[tid] = sum;
    __syncthreads();
    for (int off = 1; off < 128; off <<= 1) {
        unsigned t = (tid >= off) ? s_part[tid - off] : 0u;
        __syncthreads();
        s_part[tid] += t;
        __syncthreads();
    }
    unsigned run = (tid > 0) ? s_part[tid - 1] : 0u;
    for (int i = start; i < end; ++i) {
        unsigned c = g_count[i];
        g_offset[i] = run;
        run += c;
    }
    __syncthreads();

    for (int slot = tid; slot < OUT_VEC4; slot += 128) {
        const unsigned p0 = ((unsigned)slot * 4u) / 3u;
        float t[6];
        #pragma unroll
        for (int q = 0; q < 2; ++q) {
            unsigned p = p0 + (unsigned)q;
            float* x = &t[3 * q];
            if (p >= total) { x[0] = -1.f; x[1] = -1.f; x[2] = -1.f; continue; }
            int lo = 0, hi = NROW - 1;
            while (lo < hi) {
                int mid = (lo + hi + 1) >> 1;
                if (g_offset[mid] <= p) lo = mid; else hi = mid - 1;
            }
            int rank = (int)(p - g_offset[lo]);
            unsigned w0 = g_bitmap[lo * 3 + 0];
            unsigned w1 = g_bitmap[lo * 3 + 1];
            unsigned w2 = g_bitmap[lo * 3 + 2];
            int c0 = __popc(w0), c1 = __popc(w1);
            int bw;
            if (rank < c0)            bw = nth_set_bit(w0, rank);
            else if (rank - c0 < c1)  bw = 32 + nth_set_bit(w1, rank - c0);
            else                      bw = 64 + nth_set_bit(w2, rank - c0 - c1);
            x[0] = (float)(lo / BC);
            x[1] = (float)(lo % BC);
            x[2] = (float)bw;
        }
        out[slot] = phase_pack(slot % 3, t[0], t[1], t[2], t[3], t[4], t[5]);
    }
}

// ---------------------------------------------------------------------------
// Single fused kernel (R16 structure) with register cap for occupancy:
// __launch_bounds__(128, 12) forces regs <= ~42 (R16 measured 48 -> occ 52%).
//  1. 8 chunk-1 loads issue first (critical path).
//  2. Speculative dense store in the load shadow; the second position's
//     triple is derived INCREMENTALLY from the first (2 compares, not a
//     second divmod chain) to cut live registers.
//  3. Monotone-early-exit checkpoint (~92% stop at 4 rows).
//  4. One fence + one packed 64-bit atomic; last CTA validates total==NBLK.
// ---------------------------------------------------------------------------
__global__ __launch_bounds__(128, 12)
void fused_kernel(const float* __restrict__ mask, float4* __restrict__ out)
{
    const int cta = blockIdx.x;          // n*BC + bh
    const int n   = cta / BC;
    const int bh  = cta % BC;
    const int tid = threadIdx.x;

    __shared__ float4   sv4[256];        // 1024 column maxima
    __shared__ unsigned sbm[3];
    __shared__ unsigned s_total;
    __shared__ int      s_last;

    // padded window [bh*14, bh*14+16) -> unpadded rows [bh*14-1, bh*14+15)
    const int h0 = bh * BSTR - 1;
    const int hs = (h0 < 0) ? 0 : h0;
    const int he = (h0 + BHW < HH) ? (h0 + BHW) : HH;
    const int total_rows = he - hs;      // 15 (bh==0) or 16

    const float4* base = (const float4*)(mask + (size_t)n * HH * WW) + hs * W4;

    // ---- 1. chunk-1 loads first: 8 independent LDG.128 ----
    float4 x0 = base[0 * W4 + tid];
    float4 y0 = base[0 * W4 + 128 + tid];
    float4 x1 = base[1 * W4 + tid];
    float4 y1 = base[1 * W4 + 128 + tid];
    float4 x2 = base[2 * W4 + tid];
    float4 y2 = base[2 * W4 + 128 + tid];
    float4 x3 = base[3 * W4 + tid];
    float4 y3 = base[3 * W4 + 128 + tid];

    // ---- 2. speculative dense store (ALU hides in the load shadow) ----
    {
        const int slot = cta * 128 + tid;
        if (slot < OUT_VEC4) {
            const unsigned p0 = ((unsigned)slot * 4u) / 3u;
            // first triple by divmod
            unsigned nn = p0 / BC2;
            unsigned rr = p0 - nn * BC2;
            unsigned hh = rr / BC;
            unsigned ww = rr - hh * BC;
            float a0f = (float)nn, a1f = (float)hh, a2f = (float)ww;
            // second triple incrementally (p0+1): bw+1 with carries
            unsigned ww2 = ww + 1u, hh2 = hh, nn2 = nn;
            if (ww2 == BC) { ww2 = 0u; hh2 = hh + 1u;
                             if (hh2 == BC) { hh2 = 0u; nn2 = nn + 1u; } }
            float b0f, b1f, b2f;
            if (p0 + 1u < NBLK) { b0f = (float)nn2; b1f = (float)hh2; b2f = (float)ww2; }
            else                { b0f = -1.f; b1f = -1.f; b2f = -1.f; }
            out[slot] = phase_pack(slot % 3, a0f, a1f, a2f, b0f, b1f, b2f);
        }
    }

    // ---- 3. reduce + checkpoint (monotone early exit) ----
    float4 a0 = fmax4(fmax4(x0, x1), fmax4(x2, x3));
    float4 a1 = fmax4(fmax4(y0, y1), fmax4(y2, y3));
    bool done = checkpoint(a0, a1, sv4, sbm, tid);

    if (!done) {
        #pragma unroll 4
        for (int h = 4; h < total_rows; ++h) {
            a0 = fmax4(a0, base[h * W4 + tid]);
            a1 = fmax4(a1, base[h * W4 + 128 + tid]);
        }
        (void)checkpoint(a0, a1, sv4, sbm, tid);
    }

    // ---- 4. publish + packed-atomic completion tail ----
    if (tid < 3) g_bitmap[cta * 3 + tid] = sbm[tid];
    if (tid == 0) {
        const unsigned c = (unsigned)(__popc(sbm[0]) + __popc(sbm[1]) + __popc(sbm[2]));
        g_count[cta] = c;
        __threadfence();                  // publish before signaling
        unsigned long long prev =
            atomicAdd(&g_state, (1ULL << 32) + (unsigned long long)c);
        s_last  = ((unsigned)(prev >> 32) == (unsigned)(NROW - 1));
        s_total = (unsigned)(prev & 0xFFFFFFFFull) + c;
    }
    __syncthreads();
    if (!s_last) return;

    if (tid == 0) g_state = 0;           // reset for next graph replay

    if (s_total == NBLK) return;         // dense: speculative output correct

    __threadfence();                     // acquire side before reading peers
    sparse_rewrite(out, s_total, tid);   // cold; never on this input
}

// ---------------------------------------------------------------------------
extern "C" void kernel_launch(void* const* d_in, const int* in_sizes, int n_in,
                              void* d_out, int out_size)
{
    const float* mask = (const float*)d_in[0];

    fused_kernel<<<NROW, 128>>>(mask, (float4*)d_out);
}